// round 1
// baseline (speedup 1.0000x reference)
#include <cuda_runtime.h>

#define NB 16
#define NL 576
#define NH 12
#define ND 64
#define NM 8
#define NUM_STAB 1e-3f
#define RATIO 0.3535533905932738f   // 1/sqrt(8)

// ---------------- device scratch (no allocation allowed) ----------------
__device__ float g_qp[NB * NL * NH * NM];   // q' features [B,L,H,M]
__device__ float g_kp[NB * NL * NH * NM];   // k' features [B,L,H,M]
__device__ float g_mcolp[NH * 4 * NL];      // partial column sums of mask
__device__ float g_ks[NB * NH * NM];        // ks_sum [B,H,M]

// ---------------- packed f32x2 helpers ----------------
__device__ __forceinline__ unsigned long long pk2(float lo, float hi) {
    unsigned long long r;
    asm("mov.b64 %0, {%1, %2};" : "=l"(r)
        : "r"(__float_as_uint(lo)), "r"(__float_as_uint(hi)));
    return r;
}
__device__ __forceinline__ void fma2(unsigned long long& d,
                                     unsigned long long a,
                                     unsigned long long b) {
    asm("fma.rn.f32x2 %0, %1, %2, %0;" : "+l"(d) : "l"(a), "l"(b));
}
__device__ __forceinline__ void upk2(unsigned long long v, float& lo, float& hi) {
    unsigned int l, h;
    asm("mov.b64 {%0, %1}, %2;" : "=r"(l), "=r"(h) : "l"(v));
    lo = __uint_as_float(l);
    hi = __uint_as_float(h);
}

// ---------------- kernel 1: ReLU features ----------------
// grid (3456, 2), block 128. 32 rows of [64] per block; each thread computes
// one (row, m-pair) via packed fma.
__global__ void feat_kernel(const float* __restrict__ qin,
                            const float* __restrict__ kin,
                            const float* __restrict__ proj) {
    const float* x = blockIdx.y ? kin : qin;
    float* o = blockIdx.y ? g_kp : g_qp;

    __shared__ __align__(16) float sx[32][68];
    __shared__ float spt[64][8];   // proj transposed [c][m]

    int tid = threadIdx.x;
    int row0 = blockIdx.x * 32;

    // load proj (transposed) : 8x64 = 512 elements
    for (int i = tid; i < 512; i += 128) {
        int mm = i >> 6, cc = i & 63;
        spt[cc][mm] = proj[i];
    }
    // load 32 rows x 64 floats = 512 float4
    for (int i = tid; i < 512; i += 128) {
        int r = i >> 4, c4 = i & 15;
        *(float4*)&sx[r][c4 * 4] =
            ((const float4*)x)[(size_t)(row0 + r) * 16 + c4];
    }
    __syncthreads();

    int r = tid >> 2;      // 0..31
    int m2 = tid & 3;      // m-pair 0..3  -> m = 2*m2, 2*m2+1
    unsigned long long acc = 0ull;
#pragma unroll
    for (int c = 0; c < 64; c++) {
        float a = sx[r][c];
        float2 b = *(const float2*)&spt[c][m2 * 2];
        fma2(acc, pk2(a, a), pk2(b.x, b.y));
    }
    float s0, s1;
    upk2(acc, s0, s1);
    s0 = fmaxf(s0 * RATIO, 0.0f) + NUM_STAB;
    s1 = fmaxf(s1 * RATIO, 0.0f) + NUM_STAB;
    float2 res = make_float2(s0, s1);
    *(float2*)(o + (size_t)(row0 + r) * NM + m2 * 2) = res;
}

// ---------------- kernel 2: mask column partial sums ----------------
// grid (H, 4), block 576. mcolp[h,q,j] = sum_{i in quarter q} mask[h,i,j]
__global__ void mcol_kernel(const float* __restrict__ mask) {
    int h = blockIdx.x;
    int q = blockIdx.y;
    int j = threadIdx.x;
    const float* mh = mask + (size_t)h * NL * NL;
    int i0 = q * (NL / 4);
    float s0 = 0.f, s1 = 0.f, s2 = 0.f, s3 = 0.f;
#pragma unroll 4
    for (int i = 0; i < NL / 4; i += 4) {
        s0 += mh[(size_t)(i0 + i + 0) * NL + j];
        s1 += mh[(size_t)(i0 + i + 1) * NL + j];
        s2 += mh[(size_t)(i0 + i + 2) * NL + j];
        s3 += mh[(size_t)(i0 + i + 3) * NL + j];
    }
    g_mcolp[(h * 4 + q) * NL + j] = (s0 + s1) + (s2 + s3);
}

// ---------------- kernel 3: ks_sum[b,h,m] = sum_j mcol[h,j]*k'[b,j,h,m] ----
// grid (B*H), block 256 (32 j-lanes x 8 m)
__global__ void ks_kernel() {
    int bh = blockIdx.x;
    int b = bh / NH, h = bh % NH;
    int tid = threadIdx.x;
    int m = tid & 7;
    int js = tid >> 3;   // 0..31
    float s = 0.f;
    for (int j = js; j < NL; j += 32) {
        float mc = g_mcolp[(h * 4 + 0) * NL + j] + g_mcolp[(h * 4 + 1) * NL + j]
                 + g_mcolp[(h * 4 + 2) * NL + j] + g_mcolp[(h * 4 + 3) * NL + j];
        s += mc * g_kp[(((size_t)b * NL + j) * NH + h) * NM + m];
    }
    __shared__ float red[256];
    red[tid] = s;
    __syncthreads();
    for (int off = 128; off >= 8; off >>= 1) {
        if (tid < off) red[tid] += red[tid + off];
        __syncthreads();
    }
    if (tid < 8) g_ks[bh * NM + tid] = red[tid];
}

// ---------------- kernel 4: main masked-attention ----------------
// grid (L/64 = 9, B*H = 192), block 128.
// Block computes out[b, i0:i0+64, h, 0:64].
__global__ void __launch_bounds__(128)
attn_kernel(const float* __restrict__ value,
            const float* __restrict__ mask,
            float* __restrict__ out) {
    int it = blockIdx.x;
    int bh = blockIdx.y;
    int b = bh / NH, h = bh % NH;
    int i0 = it * 64;
    int tid = threadIdx.x;

    __shared__ __align__(16) float ss[32][68];   // S^T : [k-local][i-local]
    __shared__ __align__(16) float sv[32][68];   // V tile [j-local][d]
    __shared__ float4 sq4[64][2];                // q' tile
    __shared__ float4 sk4[32][2];                // k' tile
    __shared__ float sks[8];

    // load q' tile (64 rows x 8) and ks_sum
    {
        int r = tid >> 1, half = tid & 1;
        sq4[r][half] = *(const float4*)(g_qp +
            (((size_t)b * NL + i0 + r) * NH + h) * NM + half * 4);
    }
    if (tid < 8) sks[tid] = g_ks[bh * NM + tid];
    __syncthreads();

    const float* maskh = mask + (size_t)h * NL * NL;

    int ty = tid >> 4;   // 0..7  -> rows ty*8 .. ty*8+7
    int tx = tid & 15;   // 0..15 -> cols tx*4 .. tx*4+3
    unsigned long long acc[8][2];
#pragma unroll
    for (int r = 0; r < 8; r++) { acc[r][0] = 0ull; acc[r][1] = 0ull; }

    for (int j0 = 0; j0 < NL; j0 += 32) {
        __syncthreads();   // previous GEMM done reading sv/ss; phaseA done with sk4

        // load k' tile (32 x 8)
        if (tid < 64) {
            int jr = tid >> 1, half = tid & 1;
            sk4[jr][half] = *(const float4*)(g_kp +
                (((size_t)b * NL + j0 + jr) * NH + h) * NM + half * 4);
        }
        // load V tile (32 x 64)
        {
            int jj = tid >> 4;          // 0..7
            int c = (tid & 15) * 4;
#pragma unroll
            for (int t = 0; t < 4; t++) {
                int jr = jj + t * 8;
                *(float4*)&sv[jr][c] = *(const float4*)(value +
                    (((size_t)b * NL + j0 + jr) * NH + h) * (size_t)ND + c);
            }
        }
        __syncthreads();

        // phase A: S^T[j][i] = (q'_i . k'_j) * mask[h, i0+i, j0+j]
        {
            int j = tid & 31;
            int ibase = (tid >> 5) * 16;   // 4 groups x 16 rows
            float mv[16];
#pragma unroll
            for (int r = 0; r < 16; r++)
                mv[r] = maskh[(size_t)(i0 + ibase + r) * NL + j0 + j];
            float4 kk0 = sk4[j][0], kk1 = sk4[j][1];
#pragma unroll
            for (int r = 0; r < 16; r++) {
                int i = ibase + r;
                float4 q0 = sq4[i][0], q1 = sq4[i][1];
                float s = q0.x * kk0.x + q0.y * kk0.y + q0.z * kk0.z + q0.w * kk0.w
                        + q1.x * kk1.x + q1.y * kk1.y + q1.z * kk1.z + q1.w * kk1.w;
                ss[j][i] = s * mv[r];
            }
        }
        __syncthreads();

        // phase B: acc[64x64] += S[64x32] @ V[32x64] with packed fma.f32x2
#pragma unroll 8
        for (int kk = 0; kk < 32; kk++) {
            float4 a0 = *(const float4*)&ss[kk][ty * 8];
            float4 a1 = *(const float4*)&ss[kk][ty * 8 + 4];
            float4 vv = *(const float4*)&sv[kk][tx * 4];
            unsigned long long vp0 = pk2(vv.x, vv.y);
            unsigned long long vp1 = pk2(vv.z, vv.w);
            unsigned long long a;
            a = pk2(a0.x, a0.x); fma2(acc[0][0], a, vp0); fma2(acc[0][1], a, vp1);
            a = pk2(a0.y, a0.y); fma2(acc[1][0], a, vp0); fma2(acc[1][1], a, vp1);
            a = pk2(a0.z, a0.z); fma2(acc[2][0], a, vp0); fma2(acc[2][1], a, vp1);
            a = pk2(a0.w, a0.w); fma2(acc[3][0], a, vp0); fma2(acc[3][1], a, vp1);
            a = pk2(a1.x, a1.x); fma2(acc[4][0], a, vp0); fma2(acc[4][1], a, vp1);
            a = pk2(a1.y, a1.y); fma2(acc[5][0], a, vp0); fma2(acc[5][1], a, vp1);
            a = pk2(a1.z, a1.z); fma2(acc[6][0], a, vp0); fma2(acc[6][1], a, vp1);
            a = pk2(a1.w, a1.w); fma2(acc[7][0], a, vp0); fma2(acc[7][1], a, vp1);
        }
    }

    // epilogue: divide by normalizer = q'_i . ks_sum, write out
#pragma unroll
    for (int r = 0; r < 8; r++) {
        int i = ty * 8 + r;
        float4 q0 = sq4[i][0], q1 = sq4[i][1];
        float nrm = q0.x * sks[0] + q0.y * sks[1] + q0.z * sks[2] + q0.w * sks[3]
                  + q1.x * sks[4] + q1.y * sks[5] + q1.z * sks[6] + q1.w * sks[7];
        float inv = 1.0f / nrm;
        float o0, o1, o2, o3;
        upk2(acc[r][0], o0, o1);
        upk2(acc[r][1], o2, o3);
        float4 res = make_float4(o0 * inv, o1 * inv, o2 * inv, o3 * inv);
        *(float4*)(out + (((size_t)b * NL + i0 + i) * NH + h) * (size_t)ND + tx * 4) = res;
    }
}

// ---------------- launch ----------------
extern "C" void kernel_launch(void* const* d_in, const int* in_sizes, int n_in,
                              void* d_out, int out_size) {
    const float* q    = (const float*)d_in[0];
    const float* k    = (const float*)d_in[1];
    const float* v    = (const float*)d_in[2];
    const float* proj = (const float*)d_in[3];
    const float* mask = (const float*)d_in[4];
    float* out = (float*)d_out;

    feat_kernel<<<dim3((NB * NL * NH) / 32, 2), 128>>>(q, k, proj);
    mcol_kernel<<<dim3(NH, 4), NL>>>(mask);
    ks_kernel<<<NB * NH, 256>>>();
    attn_kernel<<<dim3(NL / 64, NB * NH), 128>>>(v, mask, out);
}